// round 17
// baseline (speedup 1.0000x reference)
#include <cuda_runtime.h>
#include <cuda_fp16.h>
#include <math.h>

typedef unsigned int u32;

// Problem constants
#define BATCH 2
#define SEQ   2048
#define DMODEL 1024
#define NHEAD 16
#define HD    64
#define MTOT  (BATCH*SEQ)
#define NQT   (SEQ/128)

// ---------------- scratch ----------------
__device__ float g_q[BATCH*SEQ*DMODEL];
__device__ float g_k[BATCH*SEQ*DMODEL];
__device__ float g_v[BATCH*SEQ*DMODEL];
__device__ float g_attn[BATCH*SEQ*DMODEL];

// ---------------- helpers ----------------
__device__ __forceinline__ u32 pack_h2(float a, float b) {
    __half2 h = __floats2half2_rn(a, b);   // lo = a, hi = b
    return *(u32*)&h;
}
__device__ __forceinline__ void mma_f16(float* d, const u32* a, const u32* b) {
    asm volatile(
        "mma.sync.aligned.m16n8k16.row.col.f32.f16.f16.f32 "
        "{%0,%1,%2,%3},{%4,%5,%6,%7},{%8,%9},{%0,%1,%2,%3};"
        : "+f"(d[0]), "+f"(d[1]), "+f"(d[2]), "+f"(d[3])
        : "r"(a[0]), "r"(a[1]), "r"(a[2]), "r"(a[3]), "r"(b[0]), "r"(b[1]));
}
__device__ __forceinline__ u32 ldh2(const __half* p) {
    return *(const u32*)p;
}

// ---------------- GEMM: fp16 mma, 128x256 tile, 64x64 warp tile (round-15, unchanged) ----------------
#define GBM 128
#define GBN 256
#define GBK 32
#define AHS 40
#define AHSTG (GBM*AHS)
#define WHSTG (GBN*AHS)

__global__ __launch_bounds__(256, 1) void gemm_h(
    const float* __restrict__ A, const float* __restrict__ W,
    const float* __restrict__ bias, float* __restrict__ C,
    int M, int N, int K)
{
    extern __shared__ __half hsm[];
    __half* Ah = hsm;
    __half* Wh = hsm + 2 * AHSTG;

    const int tid  = threadIdx.x;
    const int warp = tid >> 5;
    const int lane = tid & 31;
    const int g    = lane >> 2;
    const int t4   = lane & 3;
    const int wm   = warp >> 2;
    const int wn   = warp & 3;
    const int m0   = blockIdx.y * GBM;
    const int n0   = blockIdx.x * GBN;

    float acc[4][8][4];
#pragma unroll
    for (int i = 0; i < 4; i++)
#pragma unroll
        for (int j = 0; j < 8; j++)
#pragma unroll
            for (int r = 0; r < 4; r++) acc[i][j][r] = 0.f;

    float4 ar[4], wr4[8];
    const int skq = (tid & 7) * 4;
    int srA[4], srW[8];
#pragma unroll
    for (int l = 0; l < 4; l++) srA[l] = (tid + 256 * l) >> 3;
#pragma unroll
    for (int l = 0; l < 8; l++) srW[l] = (tid + 256 * l) >> 3;

#pragma unroll
    for (int l = 0; l < 4; l++)
        ar[l] = *(const float4*)&A[(size_t)(m0 + srA[l]) * K + skq];
#pragma unroll
    for (int l = 0; l < 8; l++)
        wr4[l] = *(const float4*)&W[(size_t)(n0 + srW[l]) * K + skq];

    const int NKB = K / GBK;
    for (int kb = 0; kb < NKB; kb++) {
        const int buf = kb & 1;
        __half* Ab = Ah + buf * AHSTG;
        __half* Wb = Wh + buf * WHSTG;

#pragma unroll
        for (int l = 0; l < 4; l++) {
            uint2 u;
            u.x = pack_h2(ar[l].x, ar[l].y);
            u.y = pack_h2(ar[l].z, ar[l].w);
            *(uint2*)&Ab[srA[l] * AHS + skq] = u;
        }
#pragma unroll
        for (int l = 0; l < 8; l++) {
            uint2 u;
            u.x = pack_h2(wr4[l].x, wr4[l].y);
            u.y = pack_h2(wr4[l].z, wr4[l].w);
            *(uint2*)&Wb[srW[l] * AHS + skq] = u;
        }

        if (kb + 1 < NKB) {
            int k0 = (kb + 1) * GBK;
#pragma unroll
            for (int l = 0; l < 4; l++)
                ar[l] = *(const float4*)&A[(size_t)(m0 + srA[l]) * K + k0 + skq];
#pragma unroll
            for (int l = 0; l < 8; l++)
                wr4[l] = *(const float4*)&W[(size_t)(n0 + srW[l]) * K + k0 + skq];
        }

        __syncthreads();

#pragma unroll
        for (int ks = 0; ks < 2; ks++) {
            const int k0 = ks * 16;
            u32 af[4][4];
#pragma unroll
            for (int i = 0; i < 4; i++) {
                int rb = wm * 64 + i * 16 + g;
                af[i][0] = ldh2(&Ab[(rb)     * AHS + k0 + 2 * t4]);
                af[i][1] = ldh2(&Ab[(rb + 8) * AHS + k0 + 2 * t4]);
                af[i][2] = ldh2(&Ab[(rb)     * AHS + k0 + 2 * t4 + 8]);
                af[i][3] = ldh2(&Ab[(rb + 8) * AHS + k0 + 2 * t4 + 8]);
            }
#pragma unroll
            for (int j = 0; j < 8; j++) {
                int nb = wn * 64 + j * 8 + g;
                u32 bf[2];
                bf[0] = ldh2(&Wb[nb * AHS + k0 + 2 * t4]);
                bf[1] = ldh2(&Wb[nb * AHS + k0 + 2 * t4 + 8]);
#pragma unroll
                for (int i = 0; i < 4; i++)
                    mma_f16(acc[i][j], af[i], bf);
            }
        }
        __syncthreads();
    }

#pragma unroll
    for (int j = 0; j < 8; j++) {
        int col = n0 + wn * 64 + j * 8 + 2 * t4;
        float b0 = bias[col], b1 = bias[col + 1];
#pragma unroll
        for (int i = 0; i < 4; i++) {
            int r0 = m0 + wm * 64 + i * 16 + g;
            float2 o0 = { acc[i][j][0] + b0, acc[i][j][1] + b1 };
            float2 o1 = { acc[i][j][2] + b0, acc[i][j][3] + b1 };
            *(float2*)&C[(size_t)r0 * N + col]       = o0;
            *(float2*)&C[(size_t)(r0 + 8) * N + col] = o1;
        }
    }
}

// ---------------- Flash attention, fp16 mma, 3-stage K/V ring, 1 barrier/tile ----------------
#define QHS 72                       // Qh/Kh row stride (halves)
#define VHS 66                       // Vt row stride (halves): 2-way store conflicts max
#define AH_Q 0                       // Qh: 128*72 = 9216 halves
#define KV_BASE (128*QHS)
#define KH_SZ (64*QHS)               // 4608 halves
#define VT_SZ (64*VHS)               // 4224 halves
#define STG_H (KH_SZ + VT_SZ)        // 8832 halves per stage
#define AH_TOT (KV_BASE + 3*STG_H)   // 9216 + 26496 = 35712 halves = 71424 B

__global__ __launch_bounds__(256, 2) void attn_kernel(
    const float* __restrict__ Q, const float* __restrict__ Kb,
    const float* __restrict__ Vb, float* __restrict__ O)
{
    extern __shared__ __half ash[];
    __half* Qh = ash + AH_Q;

    const int tid  = threadIdx.x;
    const int warp = tid >> 5;
    const int lane = tid & 31;
    const int g    = lane >> 2;
    const int t4   = lane & 3;

    const int h = blockIdx.y;
    const int b = blockIdx.z;
    const size_t base = ((size_t)b * SEQ) * DMODEL + (size_t)h * HD;
    const float scale = 0.125f;
    const int w16 = warp * 16;

    // convert K/V tile jt (LDG fp32 -> half) into ring stage st
    auto convert_tile = [&](int jt, int st) {
        __half* Kh = ash + KV_BASE + st * STG_H;
        __half* Vt = Kh + KH_SZ;
#pragma unroll
        for (int l = 0; l < 4; l++) {
            int idx = tid + l * 256;
            int row = idx >> 4;
            int col = (idx & 15) * 4;
            size_t gaddr = base + (size_t)(jt * 64 + row) * DMODEL + col;

            float4 kv = *(const float4*)&Kb[gaddr];
            uint2 u;
            u.x = pack_h2(kv.x, kv.y);
            u.y = pack_h2(kv.z, kv.w);
            *(uint2*)&Kh[row * QHS + col] = u;

            float4 vv = *(const float4*)&Vb[gaddr];
            Vt[(col + 0) * VHS + row] = __float2half_rn(vv.x);
            Vt[(col + 1) * VHS + row] = __float2half_rn(vv.y);
            Vt[(col + 2) * VHS + row] = __float2half_rn(vv.z);
            Vt[(col + 3) * VHS + row] = __float2half_rn(vv.w);
        }
    };

    for (int half_i = 0; half_i < 2; half_i++) {
        const int qtile = half_i ? (int)blockIdx.x : (NQT - 1 - (int)blockIdx.x);
        const int q0 = qtile * 128;

        __syncthreads();   // previous half's compute fully done before Qh/ring reuse

        // Q tile (128x64) -> half, pre-scaled
#pragma unroll
        for (int l = 0; l < 8; l++) {
            int idx = tid + l * 256;
            int row = idx >> 4;
            int col = (idx & 15) * 4;
            float4 v = *(const float4*)&Q[base + (size_t)(q0 + row) * DMODEL + col];
            uint2 u;
            u.x = pack_h2(v.x * scale, v.y * scale);
            u.y = pack_h2(v.z * scale, v.w * scale);
            *(uint2*)&Qh[row * QHS + col] = u;
        }

        float of[8][4];
#pragma unroll
        for (int j = 0; j < 8; j++)
#pragma unroll
            for (int r = 0; r < 4; r++) of[j][r] = 0.f;
        float m0r = -1e30f, m1r = -1e30f, l0r = 0.f, l1r = 0.f;

        const int ntiles = 2 * qtile + 2;

        convert_tile(0, 0);   // prologue

        for (int jt = 0; jt < ntiles; jt++) {
            // convert next tile into ring stage (jt+1)%3 — last read at compute(jt-2),
            // separated from here by barrier(jt-1): safe with ONE barrier per tile.
            if (jt + 1 < ntiles) convert_tile(jt + 1, (jt + 1) % 3);
            __syncthreads();

            const __half* Kh = ash + KV_BASE + (jt % 3) * STG_H;
            const __half* Vt = Kh + KH_SZ;

            // ---- S = Q @ K^T ----
            float s[8][4];
#pragma unroll
            for (int j = 0; j < 8; j++)
#pragma unroll
                for (int r = 0; r < 4; r++) s[j][r] = 0.f;

#pragma unroll
            for (int ks = 0; ks < 4; ks++) {
                const int k0 = ks * 16;
                u32 aq[4];
                aq[0] = ldh2(&Qh[(w16 + g)     * QHS + k0 + 2 * t4]);
                aq[1] = ldh2(&Qh[(w16 + g + 8) * QHS + k0 + 2 * t4]);
                aq[2] = ldh2(&Qh[(w16 + g)     * QHS + k0 + 2 * t4 + 8]);
                aq[3] = ldh2(&Qh[(w16 + g + 8) * QHS + k0 + 2 * t4 + 8]);
#pragma unroll
                for (int j = 0; j < 8; j++) {
                    u32 bfr[2];
                    bfr[0] = ldh2(&Kh[(j * 8 + g) * QHS + k0 + 2 * t4]);
                    bfr[1] = ldh2(&Kh[(j * 8 + g) * QHS + k0 + 2 * t4 + 8]);
                    mma_f16(s[j], aq, bfr);
                }
            }

            // ---- causal mask (diagonal tiles only) ----
            if (jt >= 2 * qtile) {
                int r0 = q0 + w16 + g, r1 = r0 + 8;
#pragma unroll
                for (int j = 0; j < 8; j++) {
                    int c = jt * 64 + j * 8 + 2 * t4;
                    if (c     > r0) s[j][0] = -1e30f;
                    if (c + 1 > r0) s[j][1] = -1e30f;
                    if (c     > r1) s[j][2] = -1e30f;
                    if (c + 1 > r1) s[j][3] = -1e30f;
                }
            }

            // ---- online softmax ----
            float mt0 = -1e30f, mt1 = -1e30f;
#pragma unroll
            for (int j = 0; j < 8; j++) {
                mt0 = fmaxf(mt0, fmaxf(s[j][0], s[j][1]));
                mt1 = fmaxf(mt1, fmaxf(s[j][2], s[j][3]));
            }
            mt0 = fmaxf(mt0, __shfl_xor_sync(0xffffffffu, mt0, 1));
            mt0 = fmaxf(mt0, __shfl_xor_sync(0xffffffffu, mt0, 2));
            mt1 = fmaxf(mt1, __shfl_xor_sync(0xffffffffu, mt1, 1));
            mt1 = fmaxf(mt1, __shfl_xor_sync(0xffffffffu, mt1, 2));

            float mn0 = fmaxf(m0r, mt0), mn1 = fmaxf(m1r, mt1);
            float corr0 = __expf(m0r - mn0), corr1 = __expf(m1r - mn1);
            m0r = mn0; m1r = mn1;

            float ps0 = 0.f, ps1 = 0.f;
#pragma unroll
            for (int j = 0; j < 8; j++) {
                s[j][0] = __expf(s[j][0] - mn0); ps0 += s[j][0];
                s[j][1] = __expf(s[j][1] - mn0); ps0 += s[j][1];
                s[j][2] = __expf(s[j][2] - mn1); ps1 += s[j][2];
                s[j][3] = __expf(s[j][3] - mn1); ps1 += s[j][3];
            }
            ps0 += __shfl_xor_sync(0xffffffffu, ps0, 1);
            ps0 += __shfl_xor_sync(0xffffffffu, ps0, 2);
            ps1 += __shfl_xor_sync(0xffffffffu, ps1, 1);
            ps1 += __shfl_xor_sync(0xffffffffu, ps1, 2);
            l0r = l0r * corr0 + ps0;
            l1r = l1r * corr1 + ps1;

#pragma unroll
            for (int j = 0; j < 8; j++) {
                of[j][0] *= corr0; of[j][1] *= corr0;
                of[j][2] *= corr1; of[j][3] *= corr1;
            }

            // ---- O += P @ V (A-fragment packed straight from C-fragments) ----
#pragma unroll
            for (int ks = 0; ks < 4; ks++) {
                const int k0 = ks * 16;
                u32 pa[4];
                pa[0] = pack_h2(s[2*ks][0],   s[2*ks][1]);
                pa[1] = pack_h2(s[2*ks][2],   s[2*ks][3]);
                pa[2] = pack_h2(s[2*ks+1][0], s[2*ks+1][1]);
                pa[3] = pack_h2(s[2*ks+1][2], s[2*ks+1][3]);
#pragma unroll
                for (int j = 0; j < 8; j++) {
                    u32 vf[2];
                    vf[0] = ldh2(&Vt[(j * 8 + g) * VHS + k0 + 2 * t4]);
                    vf[1] = ldh2(&Vt[(j * 8 + g) * VHS + k0 + 2 * t4 + 8]);
                    mma_f16(of[j], pa, vf);
                }
            }
        }

        // ---- epilogue ----
        float inv0 = 1.f / l0r, inv1 = 1.f / l1r;
        int r0 = q0 + w16 + g, r1 = r0 + 8;
#pragma unroll
        for (int j = 0; j < 8; j++) {
            int col = j * 8 + 2 * t4;
            float2 o0 = { of[j][0] * inv0, of[j][1] * inv0 };
            float2 o1 = { of[j][2] * inv1, of[j][3] * inv1 };
            *(float2*)&O[base + (size_t)r0 * DMODEL + col] = o0;
            *(float2*)&O[base + (size_t)r1 * DMODEL + col] = o1;
        }
    }
}

// ---------------- launch ----------------
extern "C" void kernel_launch(void* const* d_in, const int* in_sizes, int n_in,
                              void* d_out, int out_size)
{
    const float* x  = (const float*)d_in[0];
    const float* wq = (const float*)d_in[1];
    const float* bq = (const float*)d_in[2];
    const float* wk = (const float*)d_in[3];
    const float* bk = (const float*)d_in[4];
    const float* wv = (const float*)d_in[5];
    const float* bv = (const float*)d_in[6];
    const float* wo = (const float*)d_in[7];
    const float* bo = (const float*)d_in[8];
    float* out = (float*)d_out;

    float *qb, *kb, *vb, *ab;
    cudaGetSymbolAddress((void**)&qb, g_q);
    cudaGetSymbolAddress((void**)&kb, g_k);
    cudaGetSymbolAddress((void**)&vb, g_v);
    cudaGetSymbolAddress((void**)&ab, g_attn);

    const int smem_gemm = 2 * (AHSTG + WHSTG) * (int)sizeof(__half);   // 61440 B
    cudaFuncSetAttribute(gemm_h, cudaFuncAttributeMaxDynamicSharedMemorySize, smem_gemm);

    dim3 gdim(DMODEL / GBN, MTOT / GBM);   // (4, 32) = 128 blocks
    gemm_h<<<gdim, 256, smem_gemm>>>(x, wq, bq, qb, MTOT, DMODEL, DMODEL);
    gemm_h<<<gdim, 256, smem_gemm>>>(x, wk, bk, kb, MTOT, DMODEL, DMODEL);
    gemm_h<<<gdim, 256, smem_gemm>>>(x, wv, bv, vb, MTOT, DMODEL, DMODEL);

    const int smem_attn = AH_TOT * (int)sizeof(__half);   // 71424 B
    cudaFuncSetAttribute(attn_kernel, cudaFuncAttributeMaxDynamicSharedMemorySize, smem_attn);
    attn_kernel<<<dim3(NQT / 2, NHEAD, BATCH), 256, smem_attn>>>(qb, kb, vb, ab);

    gemm_h<<<gdim, 256, smem_gemm>>>(ab, wo, bo, out, MTOT, DMODEL, DMODEL);
}